// round 16
// baseline (speedup 1.0000x reference)
#include <cuda_runtime.h>
#include <cuda_bf16.h>
#include <math.h>
#include <cstdint>

// ---------------- static problem sizes ----------------
#define NB     32
#define SEQ    1024
#define NTOT   (NB*SEQ)     // 32768
#define DIM    128
#define NHEAD  4
#define HDIM   32
#define NLAY   3
#define DFF    2048
#define INDIM  64

// GEMM packed-bf16 smem: tile = 128 rows x 40 words (32 payload + 8 pad)
#define TW     (128*40)
#define SMEM_G (4*TW*4)      // 81920 bytes -> 2 CTA/SM

// packed weight buffer offsets (word units == original element count)
#define OFF_WIN   0
#define SZ_WIN    (DIM*INDIM)
#define LAYER_SZ  (3*DIM*DIM + DIM*DIM + DFF*DIM + DIM*DFF)
#define OFF_QKV(l) (SZ_WIN + (l)*LAYER_SZ)
#define OFF_WO(l)  (OFF_QKV(l) + 3*DIM*DIM)
#define OFF_W1(l)  (OFF_WO(l) + DIM*DIM)
#define OFF_W2(l)  (OFF_W1(l) + DFF*DIM)
#define WTOT      (SZ_WIN + NLAY*LAYER_SZ)

// ---------------- scratch (device globals; no allocs allowed) ---------------
__device__ float    g_h   [NTOT * DIM];
__device__ float    g_qkv [NTOT * 3*DIM];
__device__ float    g_attn[NTOT * DIM];
__device__ float    g_ffn [NTOT * DFF];
__device__ float    g_mask[NTOT];
__device__ uint32_t g_Wsp [WTOT];        // packed bf16x2 weights
__device__ float    g_pool[NB * 8 * DIM];
__device__ float    g_pm  [NB * 8];

__device__ __forceinline__ float* sel_buf(int id, const float* ext) {
    switch (id) {
        case 0: return g_h;
        case 1: return g_qkv;
        case 2: return g_attn;
        case 4: return g_ffn;
        default: return (float*)ext;
    }
}

// ---------------- small PTX helpers ----------------
__device__ __forceinline__ uint32_t cvta_smem(const void* p) {
    uint32_t a;
    asm("{ .reg .u64 t; cvta.to.shared.u64 t, %1; cvt.u32.u64 %0, t; }"
        : "=r"(a) : "l"(p));
    return a;
}
__device__ __forceinline__ void cp16(uint32_t saddr, const void* gaddr) {
    asm volatile("cp.async.cg.shared.global [%0], [%1], 16;"
                 :: "r"(saddr), "l"(gaddr));
}
#define CP_COMMIT() asm volatile("cp.async.commit_group;" ::: "memory")
#define CP_WAIT0()  asm volatile("cp.async.wait_group 0;" ::: "memory")

// bf16 m16n8k16
__device__ __forceinline__ void mma16(float* d, uint32_t a0, uint32_t a1,
                                      uint32_t a2, uint32_t a3,
                                      uint32_t b0, uint32_t b1) {
    asm volatile(
        "mma.sync.aligned.m16n8k16.row.col.f32.bf16.bf16.f32 "
        "{%0,%1,%2,%3}, {%4,%5,%6,%7}, {%8,%9}, {%0,%1,%2,%3};"
        : "+f"(d[0]), "+f"(d[1]), "+f"(d[2]), "+f"(d[3])
        : "r"(a0), "r"(a1), "r"(a2), "r"(a3), "r"(b0), "r"(b1));
}

__device__ __forceinline__ uint32_t bfpack(float x0, float x1) {
    uint32_t w;
    asm("cvt.rn.bf16x2.f32 %0, %1, %2;" : "=r"(w) : "f"(x1), "f"(x0));
    return w;
}
__device__ __forceinline__ uint32_t bflo(uint32_t whi, float x0, float x1) {
    float h0 = __uint_as_float(whi << 16);
    float h1 = __uint_as_float(whi & 0xFFFF0000u);
    return bfpack(x0 - h0, x1 - h1);
}

// ---------------- weight split/pack (single launch, grid.y = region) --------
__global__ void __launch_bounds__(256) wsplit_k(
    const float* __restrict__ W_in, const float* __restrict__ Wqkv,
    const float* __restrict__ Wo,   const float* __restrict__ W1,
    const float* __restrict__ W2)
{
    const int r = blockIdx.y;
    const float* src; int K, off, pairs;
    if (r == 0) { src = W_in; K = INDIM; off = OFF_WIN; pairs = DIM*INDIM/2; }
    else {
        const int l = (r - 1) >> 2, m = (r - 1) & 3;
        switch (m) {
          case 0: src = Wqkv + (size_t)l*3*DIM*DIM; K = DIM; off = OFF_QKV(l); pairs = 3*DIM*DIM/2; break;
          case 1: src = Wo   + (size_t)l*DIM*DIM;   K = DIM; off = OFF_WO(l);  pairs = DIM*DIM/2;   break;
          case 2: src = W1   + (size_t)l*DFF*DIM;   K = DIM; off = OFF_W1(l);  pairs = DFF*DIM/2;   break;
          default:src = W2   + (size_t)l*DIM*DFF;   K = DFF; off = OFF_W2(l);  pairs = DIM*DFF/2;   break;
        }
    }
    const int idx = blockIdx.x * 256 + threadIdx.x;
    if (idx >= pairs) return;
    const int kp  = K >> 1;
    const int row = idx / kp;
    const int k0  = (idx - row * kp) * 2;
    const float x0 = src[row * K + k0];
    const float x1 = src[row * K + k0 + 1];
    const uint32_t whi = bfpack(x0, x1);
    const uint32_t wlo = bflo(whi, x0, x1);
    const int ch = k0 >> 5;
    const int pl = (k0 & 31) >> 1;
    const int s  = pl >> 3, t = pl & 7;
    const int w  = (t < 4) ? 2*t : 2*(t-4) + 1;
    const int base = off + row * K + ch * 32 + s * 8 + w;
    g_Wsp[base]      = whi;
    g_Wsp[base + 16] = wlo;
}

// ---------------- bf16x2 GEMM, warp grid 2(m)x4(n), warp tile 64x32 ---------
template<bool RELU, bool LN>
__global__ void __launch_bounds__(256, 2) gemm_k(
    int aid, const float* __restrict__ aext,
    int woff, const float* __restrict__ bias,
    int cid, int Ncols, int K,
    const float* __restrict__ lng, const float* __restrict__ lnb)
{
    extern __shared__ uint32_t smw[];
    uint32_t* Abuf[2] = { smw,          smw + 2*TW };
    uint32_t* Bbuf[2] = { smw + TW,     smw + 3*TW };

    const float* A = sel_buf(aid, aext);
    float*       C = sel_buf(cid, nullptr);

    const int bm = blockIdx.y * 128;
    const int bn = blockIdx.x * 128;

    const int tid  = threadIdx.x;
    const int lane = tid & 31;
    const int warp = tid >> 5;
    const int wm   = warp & 1;      // 2 m-positions (64 rows each)
    const int wn   = warp >> 1;     // 4 n-positions (32 cols each)
    const int g    = lane >> 2;
    const int tg   = lane & 3;

    const int lrow  = tid >> 1;
    const int lhalf = tid & 1;
    const float*    Abase = A + (size_t)(bm + lrow) * K + lhalf * 16;
    const uint32_t* Bbase = g_Wsp + woff + (size_t)(bn + lrow) * K + lhalf * 16;
    const uint32_t  sB[2] = { cvta_smem(Bbuf[0]), cvta_smem(Bbuf[1]) };
    const uint32_t  bdst  = (uint32_t)((lrow * 40 + lhalf * 16) * 4);
    uint32_t* Asts[2] = { Abuf[0] + lrow * 40 + lhalf * 8,
                          Abuf[1] + lrow * 40 + lhalf * 8 };

    float acc[4][4][4];
    #pragma unroll
    for (int mf = 0; mf < 4; mf++)
        #pragma unroll
        for (int nf = 0; nf < 4; nf++)
            #pragma unroll
            for (int j = 0; j < 4; j++) acc[mf][nf][j] = 0.f;

    const int nch = K >> 5;

    #pragma unroll
    for (int c = 0; c < 4; c++)
        cp16(sB[0] + bdst + c * 16, Bbase + c * 4);
    CP_COMMIT();
    float4 pa[4];
    #pragma unroll
    for (int c = 0; c < 4; c++)
        pa[c] = *(const float4*)(Abase + c * 4);

    for (int ch = 0; ch < nch; ch++) {
        const int cur = ch & 1;

        {
            const float x[16] = { pa[0].x, pa[0].y, pa[0].z, pa[0].w,
                                  pa[1].x, pa[1].y, pa[1].z, pa[1].w,
                                  pa[2].x, pa[2].y, pa[2].z, pa[2].w,
                                  pa[3].x, pa[3].y, pa[3].z, pa[3].w };
            uint32_t whi[8], wlo[8];
            #pragma unroll
            for (int t = 0; t < 4; t++) {
                whi[2*t]   = bfpack(x[2*t],     x[2*t+1]);
                wlo[2*t]   = bflo(whi[2*t],   x[2*t],   x[2*t+1]);
                whi[2*t+1] = bfpack(x[2*t+8],   x[2*t+9]);
                wlo[2*t+1] = bflo(whi[2*t+1], x[2*t+8], x[2*t+9]);
            }
            uint32_t* ap = Asts[cur];
            *(uint4*)(ap)      = make_uint4(whi[0], whi[1], whi[2], whi[3]);
            *(uint4*)(ap + 4)  = make_uint4(whi[4], whi[5], whi[6], whi[7]);
            *(uint4*)(ap + 16) = make_uint4(wlo[0], wlo[1], wlo[2], wlo[3]);
            *(uint4*)(ap + 20) = make_uint4(wlo[4], wlo[5], wlo[6], wlo[7]);
        }
        if (ch + 1 < nch) {
            const int k0 = (ch + 1) << 5;
            #pragma unroll
            for (int c = 0; c < 4; c++)
                pa[c] = *(const float4*)(Abase + k0 + c * 4);
        }
        CP_WAIT0();
        __syncthreads();
        if (ch + 1 < nch) {
            const int nxt = cur ^ 1;
            const int k0w = (ch + 1) * 32;
            #pragma unroll
            for (int c = 0; c < 4; c++)
                cp16(sB[nxt] + bdst + c * 16, Bbase + k0w + c * 4);
            CP_COMMIT();
        }

        const uint32_t* As = Abuf[cur];
        const uint32_t* Bs = Bbuf[cur];

        #pragma unroll
        for (int s = 0; s < 2; s++) {
            uint2 ah[4][2], al[4][2];
            #pragma unroll
            for (int mf = 0; mf < 4; mf++) {
                const int base = (wm*64 + mf*16 + g) * 40 + s*8 + 2*tg;
                ah[mf][0] = *(const uint2*)(As + base);
                ah[mf][1] = *(const uint2*)(As + base + 8*40);
                al[mf][0] = *(const uint2*)(As + base + 16);
                al[mf][1] = *(const uint2*)(As + base + 8*40 + 16);
            }
            #pragma unroll
            for (int nf = 0; nf < 4; nf++) {
                const int nb = (wn*32 + nf*8 + g) * 40 + s*8 + 2*tg;
                const uint2 bh = *(const uint2*)(Bs + nb);
                const uint2 bl = *(const uint2*)(Bs + nb + 16);
                #pragma unroll
                for (int mf = 0; mf < 4; mf++) {
                    float* d = acc[mf][nf];
                    mma16(d, ah[mf][0].x, ah[mf][1].x, ah[mf][0].y, ah[mf][1].y, bh.x, bh.y);
                    mma16(d, ah[mf][0].x, ah[mf][1].x, ah[mf][0].y, ah[mf][1].y, bl.x, bl.y);
                    mma16(d, al[mf][0].x, al[mf][1].x, al[mf][0].y, al[mf][1].y, bh.x, bh.y);
                }
            }
        }
        __syncthreads();
    }

    if (!LN) {
        #pragma unroll
        for (int nf = 0; nf < 4; nf++) {
            const int col = bn + wn*32 + nf*8 + tg*2;
            const float bx = __ldg(bias + col);
            const float by = __ldg(bias + col + 1);
            #pragma unroll
            for (int mf = 0; mf < 4; mf++) {
                const int row = bm + wm*64 + mf*16 + g;
                float2 v0 = make_float2(acc[mf][nf][0] + bx, acc[mf][nf][1] + by);
                float2 v1 = make_float2(acc[mf][nf][2] + bx, acc[mf][nf][3] + by);
                if (RELU) {
                    v0.x = fmaxf(v0.x, 0.f); v0.y = fmaxf(v0.y, 0.f);
                    v1.x = fmaxf(v1.x, 0.f); v1.y = fmaxf(v1.y, 0.f);
                }
                *(float2*)(C + (size_t)row * Ncols + col)       = v0;
                *(float2*)(C + (size_t)(row + 8) * Ncols + col) = v1;
            }
        }
    } else {
        // fused resid+LN epilogue (Ncols==128, grid.x==1, C == g_h)
        // red layout: [sum: 4x128][sumsq: 4x128]
        float* red = (float*)smw;

        #pragma unroll
        for (int nf = 0; nf < 4; nf++) {
            const int col = wn*32 + nf*8 + tg*2;
            const float bx = __ldg(bias + col);
            const float by = __ldg(bias + col + 1);
            #pragma unroll
            for (int mf = 0; mf < 4; mf++) {
                const int row = bm + wm*64 + mf*16 + g;
                const float2 h0 = *(const float2*)(C + (size_t)row * DIM + col);
                const float2 h1 = *(const float2*)(C + (size_t)(row + 8) * DIM + col);
                acc[mf][nf][0] += bx + h0.x;
                acc[mf][nf][1] += by + h0.y;
                acc[mf][nf][2] += bx + h1.x;
                acc[mf][nf][3] += by + h1.y;
            }
        }
        #pragma unroll
        for (int mf = 0; mf < 4; mf++) {
            #pragma unroll
            for (int r = 0; r < 2; r++) {
                float s = 0.f, q = 0.f;
                #pragma unroll
                for (int nf = 0; nf < 4; nf++) {
                    const float v0 = acc[mf][nf][2*r], v1 = acc[mf][nf][2*r+1];
                    s += v0 + v1;
                    q = fmaf(v0, v0, q); q = fmaf(v1, v1, q);
                }
                s += __shfl_xor_sync(0xffffffffu, s, 1);
                s += __shfl_xor_sync(0xffffffffu, s, 2);
                q += __shfl_xor_sync(0xffffffffu, q, 1);
                q += __shfl_xor_sync(0xffffffffu, q, 2);
                if (tg == 0) {
                    const int lr = wm*64 + mf*16 + r*8 + g;
                    red[wn*128 + lr]       = s;
                    red[512 + wn*128 + lr] = q;
                }
            }
        }
        __syncthreads();
        float mean_[4][2], inv_[4][2];
        #pragma unroll
        for (int mf = 0; mf < 4; mf++) {
            #pragma unroll
            for (int r = 0; r < 2; r++) {
                const int lr = wm*64 + mf*16 + r*8 + g;
                const float S = red[lr] + red[128 + lr] + red[256 + lr] + red[384 + lr];
                const float Q = red[512 + lr] + red[640 + lr] + red[768 + lr] + red[896 + lr];
                const float mean = S * (1.f / DIM);
                const float var  = Q * (1.f / DIM) - mean * mean;
                mean_[mf][r] = mean;
                inv_[mf][r]  = rsqrtf(var + 1e-5f);
            }
        }
        #pragma unroll
        for (int nf = 0; nf < 4; nf++) {
            const int col = wn*32 + nf*8 + tg*2;
            const float2 ga = *(const float2*)(lng + col);
            const float2 be = *(const float2*)(lnb + col);
            #pragma unroll
            for (int mf = 0; mf < 4; mf++) {
                #pragma unroll
                for (int r = 0; r < 2; r++) {
                    const int row = bm + wm*64 + mf*16 + r*8 + g;
                    float2 v;
                    v.x = (acc[mf][nf][2*r]   - mean_[mf][r]) * inv_[mf][r] * ga.x + be.x;
                    v.y = (acc[mf][nf][2*r+1] - mean_[mf][r]) * inv_[mf][r] * ga.y + be.y;
                    *(float2*)(C + (size_t)row * DIM + col) = v;
                }
            }
        }
    }
}

// ---------------- MMA flash attention (R15: max-free softmax, bf16 PV) ------
__global__ void __launch_bounds__(128, 3) attn_k()
{
    __shared__ uint32_t Kp[32*40];           // packed bf16 K (hi +0 / lo +16)
    __shared__ uint32_t Vp[32*20];           // packed bf16 V [dim][key-words]
    __shared__ uint32_t Ps[4][32*20];        // per-warp packed P

    const int blk = blockIdx.x;
    const int qt  = blk & 7;
    const int bh  = blk >> 3;
    const int b   = bh >> 2;
    const int h   = bh & 3;
    const int tid  = threadIdx.x;
    const int lane = tid & 31;
    const int w    = tid >> 5;
    const int g    = lane >> 2;
    const int cth  = lane & 3;

    const float scale = 0.1767766952966369f;
    const float* base = g_qkv + (size_t)(b * SEQ) * (3*DIM) + h * HDIM;
    const int qbase = qt * 128 + w * 32;

    uint4 qf[2][2][2];
    #pragma unroll
    for (int mt = 0; mt < 2; mt++) {
        #pragma unroll
        for (int s = 0; s < 2; s++) {
            const float* r0 = base + (size_t)(qbase + mt*16 + g) * (3*DIM) + s*16 + 2*cth;
            const float* r1 = r0 + (size_t)8 * (3*DIM);
            const float2 a00 = *(const float2*)(r0);
            const float2 a01 = *(const float2*)(r0 + 8);
            const float2 a10 = *(const float2*)(r1);
            const float2 a11 = *(const float2*)(r1 + 8);
            const float s00x = a00.x*scale, s00y = a00.y*scale;
            const float s01x = a01.x*scale, s01y = a01.y*scale;
            const float s10x = a10.x*scale, s10y = a10.y*scale;
            const float s11x = a11.x*scale, s11y = a11.y*scale;
            const uint32_t h00 = bfpack(s00x, s00y);
            const uint32_t h10 = bfpack(s10x, s10y);
            const uint32_t h01 = bfpack(s01x, s01y);
            const uint32_t h11 = bfpack(s11x, s11y);
            qf[mt][s][0] = make_uint4(h00, h10, h01, h11);
            qf[mt][s][1] = make_uint4(bflo(h00, s00x, s00y), bflo(h10, s10x, s10y),
                                      bflo(h01, s01x, s01y), bflo(h11, s11x, s11y));
        }
    }

    float o[2][4][4];
    #pragma unroll
    for (int mt = 0; mt < 2; mt++)
        #pragma unroll
        for (int nt = 0; nt < 4; nt++)
            #pragma unroll
            for (int j = 0; j < 4; j++) o[mt][nt][j] = 0.f;
    float l_[2][2] = { {0.f, 0.f}, {0.f, 0.f} };

    const int key  = tid >> 2;
    const int dseg = (tid & 3) * 8;
    const int ks   = dseg >> 4;
    const int wb   = (dseg & 8) ? 1 : 0;
    const float* kp0 = base + DIM   + (size_t)key * (3*DIM) + dseg;
    const float* vp0 = base + 2*DIM + (size_t)key * (3*DIM) + dseg;
    uint32_t* kpr = Kp + key*40 + ks*8 + wb;
    const int vgrp = key >> 4;
    const int vp8  = (key >> 1) & 7;
    const int vwp  = (vp8 < 4) ? 2*vp8 : 2*(vp8-4) + 1;
    const uint32_t vp_u16_off = (uint32_t)(((vgrp*8 + vwp)*2 + (key & 1)) * 2);
    const uint32_t vp_base = cvta_smem(Vp);

    float4 rk0 = *(const float4*)(kp0);
    float4 rk1 = *(const float4*)(kp0 + 4);
    float4 rv0 = *(const float4*)(vp0);
    float4 rv1 = *(const float4*)(vp0 + 4);

    uint32_t* pw = Ps[w];

    for (int t = 0; t < 32; t++) {
        __syncthreads();
        {
            const float kv[8] = { rk0.x, rk0.y, rk0.z, rk0.w,
                                  rk1.x, rk1.y, rk1.z, rk1.w };
            const float vv[8] = { rv0.x, rv0.y, rv0.z, rv0.w,
                                  rv1.x, rv1.y, rv1.z, rv1.w };
            #pragma unroll
            for (int j = 0; j < 4; j++) {
                const uint32_t khi = bfpack(kv[2*j], kv[2*j+1]);
                kpr[2*j]      = khi;
                kpr[2*j + 16] = bflo(khi, kv[2*j], kv[2*j+1]);
            }
            #pragma unroll
            for (int j = 0; j < 8; j++) {
                const uint16_t hv = (uint16_t)(bfpack(vv[j], vv[j]) & 0xFFFFu);
                const uint32_t addr = vp_base + (uint32_t)((dseg + j) * 20 * 4) + vp_u16_off;
                asm volatile("st.shared.u16 [%0], %1;" :: "r"(addr), "h"(hv) : "memory");
            }
        }
        __syncthreads();
        if (t + 1 < 32) {
            const size_t off = (size_t)(t + 1) * 32 * (3*DIM);
            rk0 = *(const float4*)(kp0 + off);
            rk1 = *(const float4*)(kp0 + off + 4);
            rv0 = *(const float4*)(vp0 + off);
            rv1 = *(const float4*)(vp0 + off + 4);
        }

        float s[2][4][4];
        #pragma unroll
        for (int mt = 0; mt < 2; mt++)
            #pragma unroll
            for (int nt = 0; nt < 4; nt++)
                #pragma unroll
                for (int j = 0; j < 4; j++) s[mt][nt][j] = 0.f;

        #pragma unroll
        for (int nt = 0; nt < 4; nt++) {
            #pragma unroll
            for (int ks2 = 0; ks2 < 2; ks2++) {
                const int nb = (nt*8 + g)*40 + ks2*8 + 2*cth;
                const uint2 bh2 = *(const uint2*)(Kp + nb);
                const uint2 bl2 = *(const uint2*)(Kp + nb + 16);
                #pragma unroll
                for (int mt = 0; mt < 2; mt++) {
                    float* d = s[mt][nt];
                    const uint4 qh_ = qf[mt][ks2][0];
                    const uint4 ql_ = qf[mt][ks2][1];
                    mma16(d, qh_.x, qh_.y, qh_.z, qh_.w, bh2.x, bh2.y);
                    mma16(d, ql_.x, ql_.y, ql_.z, ql_.w, bh2.x, bh2.y);
                    mma16(d, qh_.x, qh_.y, qh_.z, qh_.w, bl2.x, bl2.y);
                }
            }
        }

        #pragma unroll
        for (int mt = 0; mt < 2; mt++) {
            #pragma unroll
            for (int r = 0; r < 2; r++) {
                float ts = 0.f;
                #pragma unroll
                for (int nt = 0; nt < 4; nt++) {
                    const float p0 = __expf(s[mt][nt][2*r]);
                    const float p1 = __expf(s[mt][nt][2*r+1]);
                    s[mt][nt][2*r]   = p0;
                    s[mt][nt][2*r+1] = p1;
                    ts += p0 + p1;
                }
                ts += __shfl_xor_sync(0xffffffffu, ts, 1);
                ts += __shfl_xor_sync(0xffffffffu, ts, 2);
                l_[mt][r] += ts;
            }
        }
        #pragma unroll
        for (int mt = 0; mt < 2; mt++)
            #pragma unroll
            for (int r = 0; r < 2; r++) {
                const int row = mt*16 + r*8 + g;
                #pragma unroll
                for (int nt = 0; nt < 4; nt++)
                    pw[row*20 + (nt>>1)*8 + 2*cth + (nt&1)] =
                        bfpack(s[mt][nt][2*r], s[mt][nt][2*r+1]);
            }
        __syncwarp();

        #pragma unroll
        for (int kc = 0; kc < 2; kc++) {
            uint2 a[2][2];
            #pragma unroll
            for (int mt = 0; mt < 2; mt++) {
                a[mt][0] = *(const uint2*)(pw + (mt*16 + g)*20 + kc*8 + 2*cth);
                a[mt][1] = *(const uint2*)(pw + (mt*16 + 8 + g)*20 + kc*8 + 2*cth);
            }
            #pragma unroll
            for (int nt = 0; nt < 4; nt++) {
                const uint2 bv = *(const uint2*)(Vp + (nt*8 + g)*20 + kc*8 + 2*cth);
                #pragma unroll
                for (int mt = 0; mt < 2; mt++)
                    mma16(o[mt][nt], a[mt][0].x, a[mt][1].x, a[mt][0].y, a[mt][1].y,
                          bv.x, bv.y);
            }
        }
        __syncwarp();
    }

    #pragma unroll
    for (int mt = 0; mt < 2; mt++) {
        #pragma unroll
        for (int r = 0; r < 2; r++) {
            const float inv = 1.f / l_[mt][r];
            const int row = qbase + mt*16 + r*8 + g;
            float* orow = g_attn + (size_t)(b * SEQ + row) * DIM + h * HDIM;
            #pragma unroll
            for (int nt = 0; nt < 4; nt++) {
                float2 v = make_float2(o[mt][nt][2*r] * inv,
                                       o[mt][nt][2*r+1] * inv);
                *(float2*)(orow + nt*8 + 2*cth) = v;
            }
        }
    }
}

// ---------------- node mask from post-projection h ---------------------------
__global__ void __launch_bounds__(256) mask_k()
{
    const int warp = threadIdx.x >> 5;
    const int lane = threadIdx.x & 31;
    const int row  = blockIdx.x * 8 + warp;
    const float* r = g_h + (size_t)row * DIM;
    float s = 0.f;
    #pragma unroll
    for (int i = 0; i < 4; i++) s += r[lane + 32*i];
    #pragma unroll
    for (int off = 16; off; off >>= 1) s += __shfl_xor_sync(~0u, s, off);
    if (lane == 0) g_mask[row] = (s != 0.f) ? 1.f : 0.f;
}

// ---------------- masked mean pooling (2 stage) -----------------------------
__global__ void __launch_bounds__(DIM) pool1_k()
{
    const int b  = blockIdx.y;
    const int c  = blockIdx.x;
    const int d  = threadIdx.x;
    float acc = 0.f, ms = 0.f;
    const int r0 = b * SEQ + c * 128;
    for (int r = 0; r < 128; r++) {
        const float mk = g_mask[r0 + r];
        acc = fmaf(g_h[(size_t)(r0 + r) * DIM + d], mk, acc);
        ms += mk;
    }
    g_pool[(b * 8 + c) * DIM + d] = acc;
    if (d == 0) g_pm[b * 8 + c] = ms;
}

__global__ void __launch_bounds__(DIM) pool2_k(float* __restrict__ out)
{
    const int b = blockIdx.x;
    const int d = threadIdx.x;
    float acc = 0.f, ms = 0.f;
    #pragma unroll
    for (int c = 0; c < 8; c++) {
        acc += g_pool[(b * 8 + c) * DIM + d];
        ms  += g_pm[b * 8 + c];
    }
    out[b * DIM + d] = acc / ms;
}

// ---------------- driver -----------------------------------------------------
extern "C" void kernel_launch(void* const* d_in, const int* in_sizes, int n_in,
                              void* d_out, int out_size)
{
    const float* x     = (const float*)d_in[0];   // [N, 64]
    const float* W_in  = (const float*)d_in[2];   // [128, 64]
    const float* b_in  = (const float*)d_in[3];   // [128]
    const float* Wqkv  = (const float*)d_in[4];   // [L, 384, 128]
    const float* bqkv  = (const float*)d_in[5];   // [L, 384]
    const float* Wo    = (const float*)d_in[6];   // [L, 128, 128]
    const float* bo    = (const float*)d_in[7];   // [L, 128]
    const float* W1    = (const float*)d_in[8];   // [L, 2048, 128]
    const float* b1    = (const float*)d_in[9];   // [L, 2048]
    const float* W2    = (const float*)d_in[10];  // [L, 128, 2048]
    const float* b2    = (const float*)d_in[11];  // [L, 128]
    const float* ln1g  = (const float*)d_in[12];
    const float* ln1b  = (const float*)d_in[13];
    const float* ln2g  = (const float*)d_in[14];
    const float* ln2b  = (const float*)d_in[15];
    float* out = (float*)d_out;

    static bool attr_done = false;
    if (!attr_done) {
        cudaFuncSetAttribute(gemm_k<false, false>,
            cudaFuncAttributeMaxDynamicSharedMemorySize, SMEM_G);
        cudaFuncSetAttribute(gemm_k<true, false>,
            cudaFuncAttributeMaxDynamicSharedMemorySize, SMEM_G);
        cudaFuncSetAttribute(gemm_k<false, true>,
            cudaFuncAttributeMaxDynamicSharedMemorySize, SMEM_G);
        attr_done = true;
    }

    wsplit_k<<<dim3(512, 1 + 4*NLAY), 256>>>(W_in, Wqkv, Wo, W1, W2);

    const int MROW = NTOT / 128;   // 256 row-tiles

    gemm_k<false, false><<<dim3(1, MROW), 256, SMEM_G>>>(
        5, x, OFF_WIN, b_in, 0, DIM, INDIM, nullptr, nullptr);
    mask_k<<<NTOT/8, 256>>>();

    for (int l = 0; l < NLAY; l++) {
        gemm_k<false, false><<<dim3(3, MROW), 256, SMEM_G>>>(
            0, nullptr, OFF_QKV(l), bqkv + l*3*DIM, 1, 3*DIM, DIM, nullptr, nullptr);
        attn_k<<<NB*NHEAD*(SEQ/128), 128>>>();
        gemm_k<false, true><<<dim3(1, MROW), 256, SMEM_G>>>(
            2, nullptr, OFF_WO(l), bo + l*DIM, 0, DIM, DIM,
            ln1g + l*DIM, ln1b + l*DIM);
        gemm_k<true, false><<<dim3(DFF/128, MROW), 256, SMEM_G>>>(
            0, nullptr, OFF_W1(l), b1 + l*DFF, 4, DFF, DIM, nullptr, nullptr);
        gemm_k<false, true><<<dim3(1, MROW), 256, SMEM_G>>>(
            4, nullptr, OFF_W2(l), b2 + l*DIM, 0, DIM, DFF,
            ln2g + l*DIM, ln2b + l*DIM);
    }

    pool1_k<<<dim3(8, NB), DIM>>>();
    pool2_k<<<NB, DIM>>>(out);
}

// round 17
// speedup vs baseline: 1.1129x; 1.1129x over previous
#include <cuda_runtime.h>
#include <cuda_bf16.h>
#include <math.h>
#include <cstdint>

// ---------------- static problem sizes ----------------
#define NB     32
#define SEQ    1024
#define NTOT   (NB*SEQ)     // 32768
#define DIM    128
#define NHEAD  4
#define HDIM   32
#define NLAY   3
#define DFF    2048
#define INDIM  64

// GEMM packed-bf16 smem: tile = 128 rows x 40 words (32 payload + 8 pad)
#define TW     (128*40)
#define SMEM_G (4*TW*4)      // 81920 bytes -> 2 CTA/SM

// packed weight buffer offsets (word units == original element count)
#define OFF_WIN   0
#define SZ_WIN    (DIM*INDIM)
#define LAYER_SZ  (3*DIM*DIM + DIM*DIM + DFF*DIM + DIM*DFF)
#define OFF_QKV(l) (SZ_WIN + (l)*LAYER_SZ)
#define OFF_WO(l)  (OFF_QKV(l) + 3*DIM*DIM)
#define OFF_W1(l)  (OFF_WO(l) + DIM*DIM)
#define OFF_W2(l)  (OFF_W1(l) + DFF*DIM)
#define WTOT      (SZ_WIN + NLAY*LAYER_SZ)

// ---------------- scratch (device globals; no allocs allowed) ---------------
__device__ float    g_h   [NTOT * DIM];
__device__ float    g_qkv [NTOT * 3*DIM];
__device__ float    g_attn[NTOT * DIM];
__device__ float    g_ffn [NTOT * DFF];
__device__ float    g_mask[NTOT];
__device__ uint32_t g_Wsp [WTOT];                  // packed bf16x2 weights
__device__ uint32_t g_kp  [NB*NHEAD*SEQ*32];       // packed K (hi 16w + lo 16w per key)
__device__ float    g_pool[NB * 8 * DIM];
__device__ float    g_pm  [NB * 8];

__device__ __forceinline__ float* sel_buf(int id, const float* ext) {
    switch (id) {
        case 0: return g_h;
        case 1: return g_qkv;
        case 2: return g_attn;
        case 4: return g_ffn;
        default: return (float*)ext;
    }
}

// ---------------- small PTX helpers ----------------
__device__ __forceinline__ uint32_t cvta_smem(const void* p) {
    uint32_t a;
    asm("{ .reg .u64 t; cvta.to.shared.u64 t, %1; cvt.u32.u64 %0, t; }"
        : "=r"(a) : "l"(p));
    return a;
}
__device__ __forceinline__ void cp16(uint32_t saddr, const void* gaddr) {
    asm volatile("cp.async.cg.shared.global [%0], [%1], 16;"
                 :: "r"(saddr), "l"(gaddr));
}
#define CP_COMMIT() asm volatile("cp.async.commit_group;" ::: "memory")
#define CP_WAIT0()  asm volatile("cp.async.wait_group 0;" ::: "memory")
#define CP_WAIT1()  asm volatile("cp.async.wait_group 1;" ::: "memory")

// bf16 m16n8k16
__device__ __forceinline__ void mma16(float* d, uint32_t a0, uint32_t a1,
                                      uint32_t a2, uint32_t a3,
                                      uint32_t b0, uint32_t b1) {
    asm volatile(
        "mma.sync.aligned.m16n8k16.row.col.f32.bf16.bf16.f32 "
        "{%0,%1,%2,%3}, {%4,%5,%6,%7}, {%8,%9}, {%0,%1,%2,%3};"
        : "+f"(d[0]), "+f"(d[1]), "+f"(d[2]), "+f"(d[3])
        : "r"(a0), "r"(a1), "r"(a2), "r"(a3), "r"(b0), "r"(b1));
}

__device__ __forceinline__ uint32_t bfpack(float x0, float x1) {
    uint32_t w;
    asm("cvt.rn.bf16x2.f32 %0, %1, %2;" : "=r"(w) : "f"(x1), "f"(x0));
    return w;
}
__device__ __forceinline__ uint32_t bflo(uint32_t whi, float x0, float x1) {
    float h0 = __uint_as_float(whi << 16);
    float h1 = __uint_as_float(whi & 0xFFFF0000u);
    return bfpack(x0 - h0, x1 - h1);
}

// ---------------- weight split/pack (single launch, grid.y = region) --------
__global__ void __launch_bounds__(256) wsplit_k(
    const float* __restrict__ W_in, const float* __restrict__ Wqkv,
    const float* __restrict__ Wo,   const float* __restrict__ W1,
    const float* __restrict__ W2)
{
    const int r = blockIdx.y;
    const float* src; int K, off, pairs;
    if (r == 0) { src = W_in; K = INDIM; off = OFF_WIN; pairs = DIM*INDIM/2; }
    else {
        const int l = (r - 1) >> 2, m = (r - 1) & 3;
        switch (m) {
          case 0: src = Wqkv + (size_t)l*3*DIM*DIM; K = DIM; off = OFF_QKV(l); pairs = 3*DIM*DIM/2; break;
          case 1: src = Wo   + (size_t)l*DIM*DIM;   K = DIM; off = OFF_WO(l);  pairs = DIM*DIM/2;   break;
          case 2: src = W1   + (size_t)l*DFF*DIM;   K = DIM; off = OFF_W1(l);  pairs = DFF*DIM/2;   break;
          default:src = W2   + (size_t)l*DIM*DFF;   K = DFF; off = OFF_W2(l);  pairs = DIM*DFF/2;   break;
        }
    }
    const int idx = blockIdx.x * 256 + threadIdx.x;
    if (idx >= pairs) return;
    const int kp  = K >> 1;
    const int row = idx / kp;
    const int k0  = (idx - row * kp) * 2;
    const float x0 = src[row * K + k0];
    const float x1 = src[row * K + k0 + 1];
    const uint32_t whi = bfpack(x0, x1);
    const uint32_t wlo = bflo(whi, x0, x1);
    const int ch = k0 >> 5;
    const int pl = (k0 & 31) >> 1;
    const int s  = pl >> 3, t = pl & 7;
    const int w  = (t < 4) ? 2*t : 2*(t-4) + 1;
    const int base = off + row * K + ch * 32 + s * 8 + w;
    g_Wsp[base]      = whi;
    g_Wsp[base + 16] = wlo;
}

// ---------------- bf16x2 GEMM (R15 config; KPK adds packed-K emission) ------
template<bool RELU, bool LN, bool KPK>
__global__ void __launch_bounds__(256, 2) gemm_k(
    int aid, const float* __restrict__ aext,
    int woff, const float* __restrict__ bias,
    int cid, int Ncols, int K,
    const float* __restrict__ lng, const float* __restrict__ lnb)
{
    extern __shared__ uint32_t smw[];
    uint32_t* Abuf[2] = { smw,          smw + 2*TW };
    uint32_t* Bbuf[2] = { smw + TW,     smw + 3*TW };

    const float* A = sel_buf(aid, aext);
    float*       C = sel_buf(cid, nullptr);

    const int bm = blockIdx.y * 128;
    const int bn = blockIdx.x * 128;

    const int tid  = threadIdx.x;
    const int lane = tid & 31;
    const int warp = tid >> 5;
    const int wm   = warp & 3;
    const int wn   = warp >> 2;
    const int g    = lane >> 2;
    const int tg   = lane & 3;

    const int lrow  = tid >> 1;
    const int lhalf = tid & 1;
    const float*    Abase = A + (size_t)(bm + lrow) * K + lhalf * 16;
    const uint32_t* Bbase = g_Wsp + woff + (size_t)(bn + lrow) * K + lhalf * 16;
    const uint32_t  sB[2] = { cvta_smem(Bbuf[0]), cvta_smem(Bbuf[1]) };
    const uint32_t  bdst  = (uint32_t)((lrow * 40 + lhalf * 16) * 4);
    uint32_t* Asts[2] = { Abuf[0] + lrow * 40 + lhalf * 8,
                          Abuf[1] + lrow * 40 + lhalf * 8 };

    float acc[2][8][4];
    #pragma unroll
    for (int mf = 0; mf < 2; mf++)
        #pragma unroll
        for (int nf = 0; nf < 8; nf++)
            #pragma unroll
            for (int j = 0; j < 4; j++) acc[mf][nf][j] = 0.f;

    const int nch = K >> 5;

    #pragma unroll
    for (int c = 0; c < 4; c++)
        cp16(sB[0] + bdst + c * 16, Bbase + c * 4);
    CP_COMMIT();
    float4 pa[4];
    #pragma unroll
    for (int c = 0; c < 4; c++)
        pa[c] = *(const float4*)(Abase + c * 4);

    for (int ch = 0; ch < nch; ch++) {
        const int cur = ch & 1;

        {
            const float x[16] = { pa[0].x, pa[0].y, pa[0].z, pa[0].w,
                                  pa[1].x, pa[1].y, pa[1].z, pa[1].w,
                                  pa[2].x, pa[2].y, pa[2].z, pa[2].w,
                                  pa[3].x, pa[3].y, pa[3].z, pa[3].w };
            uint32_t whi[8], wlo[8];
            #pragma unroll
            for (int t = 0; t < 4; t++) {
                whi[2*t]   = bfpack(x[2*t],     x[2*t+1]);
                wlo[2*t]   = bflo(whi[2*t],   x[2*t],   x[2*t+1]);
                whi[2*t+1] = bfpack(x[2*t+8],   x[2*t+9]);
                wlo[2*t+1] = bflo(whi[2*t+1], x[2*t+8], x[2*t+9]);
            }
            uint32_t* ap = Asts[cur];
            *(uint4*)(ap)      = make_uint4(whi[0], whi[1], whi[2], whi[3]);
            *(uint4*)(ap + 4)  = make_uint4(whi[4], whi[5], whi[6], whi[7]);
            *(uint4*)(ap + 16) = make_uint4(wlo[0], wlo[1], wlo[2], wlo[3]);
            *(uint4*)(ap + 20) = make_uint4(wlo[4], wlo[5], wlo[6], wlo[7]);
        }
        if (ch + 1 < nch) {
            const int k0 = (ch + 1) << 5;
            #pragma unroll
            for (int c = 0; c < 4; c++)
                pa[c] = *(const float4*)(Abase + k0 + c * 4);
        }
        CP_WAIT0();
        __syncthreads();
        if (ch + 1 < nch) {
            const int nxt = cur ^ 1;
            const int k0w = (ch + 1) * 32;
            #pragma unroll
            for (int c = 0; c < 4; c++)
                cp16(sB[nxt] + bdst + c * 16, Bbase + k0w + c * 4);
            CP_COMMIT();
        }

        const uint32_t* As = Abuf[cur];
        const uint32_t* Bs = Bbuf[cur];

        #pragma unroll
        for (int s = 0; s < 2; s++) {
            uint2 ah[2][2], al[2][2];
            #pragma unroll
            for (int mf = 0; mf < 2; mf++) {
                const int base = (wm*32 + mf*16 + g) * 40 + s*8 + 2*tg;
                ah[mf][0] = *(const uint2*)(As + base);
                ah[mf][1] = *(const uint2*)(As + base + 8*40);
                al[mf][0] = *(const uint2*)(As + base + 16);
                al[mf][1] = *(const uint2*)(As + base + 8*40 + 16);
            }
            #pragma unroll
            for (int nf = 0; nf < 8; nf++) {
                const int nb = (wn*64 + nf*8 + g) * 40 + s*8 + 2*tg;
                const uint2 bh = *(const uint2*)(Bs + nb);
                const uint2 bl = *(const uint2*)(Bs + nb + 16);
                #pragma unroll
                for (int mf = 0; mf < 2; mf++) {
                    float* d = acc[mf][nf];
                    mma16(d, ah[mf][0].x, ah[mf][1].x, ah[mf][0].y, ah[mf][1].y, bh.x, bh.y);
                    mma16(d, ah[mf][0].x, ah[mf][1].x, ah[mf][0].y, ah[mf][1].y, bl.x, bl.y);
                    mma16(d, al[mf][0].x, al[mf][1].x, al[mf][0].y, al[mf][1].y, bh.x, bh.y);
                }
            }
        }
        __syncthreads();
    }

    if (!LN) {
        const bool emitk = KPK && (blockIdx.x == 1);   // QKV K block: cols 128..255
        #pragma unroll
        for (int nf = 0; nf < 8; nf++) {
            const int col = bn + wn*64 + nf*8 + tg*2;
            const float bx = __ldg(bias + col);
            const float by = __ldg(bias + col + 1);
            // packed K word index (same formula as wsplit; col&31 == (col-128)&31)
            const int p  = (col & 31) >> 1;
            const int sc = p >> 3, tc = p & 7;
            const int wic = (tc < 4) ? 2*tc : 2*(tc-4) + 1;
            const int widx = sc*8 + wic;
            const int h = (col >> 5) & 3;    // head (valid when emitk)
            #pragma unroll
            for (int mf = 0; mf < 2; mf++) {
                const int row = bm + wm*32 + mf*16 + g;
                float2 v0 = make_float2(acc[mf][nf][0] + bx, acc[mf][nf][1] + by);
                float2 v1 = make_float2(acc[mf][nf][2] + bx, acc[mf][nf][3] + by);
                if (RELU) {
                    v0.x = fmaxf(v0.x, 0.f); v0.y = fmaxf(v0.y, 0.f);
                    v1.x = fmaxf(v1.x, 0.f); v1.y = fmaxf(v1.y, 0.f);
                }
                *(float2*)(C + (size_t)row * Ncols + col)       = v0;
                *(float2*)(C + (size_t)(row + 8) * Ncols + col) = v1;
                if (emitk) {
                    const uint32_t h0 = bfpack(v0.x, v0.y);
                    const uint32_t h1 = bfpack(v1.x, v1.y);
                    const int b0 = row >> 10, k0 = row & 1023;
                    uint32_t* p0 = g_kp + ((size_t)((b0*4 + h)*1024 + k0))*32 + widx;
                    uint32_t* p1 = g_kp + ((size_t)((b0*4 + h)*1024 + k0 + 8))*32 + widx;
                    p0[0]  = h0; p0[16] = bflo(h0, v0.x, v0.y);
                    p1[0]  = h1; p1[16] = bflo(h1, v1.x, v1.y);
                }
            }
        }
    } else {
        float* red = (float*)smw;

        #pragma unroll
        for (int nf = 0; nf < 8; nf++) {
            const int col = wn*64 + nf*8 + tg*2;
            const float bx = __ldg(bias + col);
            const float by = __ldg(bias + col + 1);
            #pragma unroll
            for (int mf = 0; mf < 2; mf++) {
                const int row = bm + wm*32 + mf*16 + g;
                const float2 h0 = *(const float2*)(C + (size_t)row * DIM + col);
                const float2 h1 = *(const float2*)(C + (size_t)(row + 8) * DIM + col);
                acc[mf][nf][0] += bx + h0.x;
                acc[mf][nf][1] += by + h0.y;
                acc[mf][nf][2] += bx + h1.x;
                acc[mf][nf][3] += by + h1.y;
            }
        }
        #pragma unroll
        for (int mf = 0; mf < 2; mf++) {
            #pragma unroll
            for (int r = 0; r < 2; r++) {
                float s = 0.f, q = 0.f;
                #pragma unroll
                for (int nf = 0; nf < 8; nf++) {
                    const float v0 = acc[mf][nf][2*r], v1 = acc[mf][nf][2*r+1];
                    s += v0 + v1;
                    q = fmaf(v0, v0, q); q = fmaf(v1, v1, q);
                }
                s += __shfl_xor_sync(0xffffffffu, s, 1);
                s += __shfl_xor_sync(0xffffffffu, s, 2);
                q += __shfl_xor_sync(0xffffffffu, q, 1);
                q += __shfl_xor_sync(0xffffffffu, q, 2);
                if (tg == 0) {
                    const int lr = wm*32 + mf*16 + r*8 + g;
                    red[wn*128 + lr]       = s;
                    red[256 + wn*128 + lr] = q;
                }
            }
        }
        __syncthreads();
        float mean_[2][2], inv_[2][2];
        #pragma unroll
        for (int mf = 0; mf < 2; mf++) {
            #pragma unroll
            for (int r = 0; r < 2; r++) {
                const int lr = wm*32 + mf*16 + r*8 + g;
                const float S = red[lr] + red[128 + lr];
                const float Q = red[256 + lr] + red[384 + lr];
                const float mean = S * (1.f / DIM);
                const float var  = Q * (1.f / DIM) - mean * mean;
                mean_[mf][r] = mean;
                inv_[mf][r]  = rsqrtf(var + 1e-5f);
            }
        }
        #pragma unroll
        for (int nf = 0; nf < 8; nf++) {
            const int col = wn*64 + nf*8 + tg*2;
            const float2 ga = *(const float2*)(lng + col);
            const float2 be = *(const float2*)(lnb + col);
            #pragma unroll
            for (int mf = 0; mf < 2; mf++) {
                #pragma unroll
                for (int r = 0; r < 2; r++) {
                    const int row = bm + wm*32 + mf*16 + r*8 + g;
                    float2 v;
                    v.x = (acc[mf][nf][2*r]   - mean_[mf][r]) * inv_[mf][r] * ga.x + be.x;
                    v.y = (acc[mf][nf][2*r+1] - mean_[mf][r]) * inv_[mf][r] * ga.y + be.y;
                    *(float2*)(C + (size_t)row * DIM + col) = v;
                }
            }
        }
    }
}

// ---------------- MMA flash attention -----------------------------------
// K pre-packed in g_kp -> pure cp.async double-buffered smem tiles.
// Softmax: max-free. PV: single-limb bf16.
__global__ void __launch_bounds__(128, 3) attn_k()
{
    __shared__ uint32_t Kp[2][32*40];        // packed K tiles (double buffer)
    __shared__ uint32_t Vp[32*20];           // packed bf16 V [dim][key-words]
    __shared__ uint32_t Ps[4][32*20];        // per-warp packed P

    const int blk = blockIdx.x;
    const int qt  = blk & 7;
    const int bh  = blk >> 3;
    const int b   = bh >> 2;
    const int h   = bh & 3;
    const int tid  = threadIdx.x;
    const int lane = tid & 31;
    const int w    = tid >> 5;
    const int g    = lane >> 2;
    const int cth  = lane & 3;

    const float scale = 0.1767766952966369f;
    const float* base = g_qkv + (size_t)(b * SEQ) * (3*DIM) + h * HDIM;
    const int qbase = qt * 128 + w * 32;

    uint4 qf[2][2][2];
    #pragma unroll
    for (int mt = 0; mt < 2; mt++) {
        #pragma unroll
        for (int s = 0; s < 2; s++) {
            const float* r0 = base + (size_t)(qbase + mt*16 + g) * (3*DIM) + s*16 + 2*cth;
            const float* r1 = r0 + (size_t)8 * (3*DIM);
            const float2 a00 = *(const float2*)(r0);
            const float2 a01 = *(const float2*)(r0 + 8);
            const float2 a10 = *(const float2*)(r1);
            const float2 a11 = *(const float2*)(r1 + 8);
            const float s00x = a00.x*scale, s00y = a00.y*scale;
            const float s01x = a01.x*scale, s01y = a01.y*scale;
            const float s10x = a10.x*scale, s10y = a10.y*scale;
            const float s11x = a11.x*scale, s11y = a11.y*scale;
            const uint32_t h00 = bfpack(s00x, s00y);
            const uint32_t h10 = bfpack(s10x, s10y);
            const uint32_t h01 = bfpack(s01x, s01y);
            const uint32_t h11 = bfpack(s11x, s11y);
            qf[mt][s][0] = make_uint4(h00, h10, h01, h11);
            qf[mt][s][1] = make_uint4(bflo(h00, s00x, s00y), bflo(h10, s10x, s10y),
                                      bflo(h01, s01x, s01y), bflo(h11, s11x, s11y));
        }
    }

    float o[2][4][4];
    #pragma unroll
    for (int mt = 0; mt < 2; mt++)
        #pragma unroll
        for (int nt = 0; nt < 4; nt++)
            #pragma unroll
            for (int j = 0; j < 4; j++) o[mt][nt][j] = 0.f;
    float l_[2][2] = { {0.f, 0.f}, {0.f, 0.f} };

    // loaders
    const int key  = tid >> 2;                  // 0..31
    const int q4   = tid & 3;                   // word quarter
    const int dseg = (tid & 3) * 8;             // V dim segment
    const uint32_t* kg = g_kp + ((size_t)((b*4 + h)*1024 + key))*32 + q4*8;
    const float*    vp0 = base + 2*DIM + (size_t)key * (3*DIM) + dseg;
    const uint32_t  sKp[2] = { cvta_smem(&Kp[0][0]), cvta_smem(&Kp[1][0]) };
    const uint32_t  kdst = (uint32_t)((key*40 + q4*8) * 4);
    const int vgrp = key >> 4;
    const int vp8  = (key >> 1) & 7;
    const int vwp  = (vp8 < 4) ? 2*vp8 : 2*(vp8-4) + 1;
    const uint32_t vp_u16_off = (uint32_t)(((vgrp*8 + vwp)*2 + (key & 1)) * 2);
    const uint32_t vp_base = cvta_smem(Vp);

    // prologue: K tile 0 async; V tile 0 regs
    cp16(sKp[0] + kdst,      kg);
    cp16(sKp[0] + kdst + 16, kg + 4);
    CP_COMMIT();
    float4 rv0 = *(const float4*)(vp0);
    float4 rv1 = *(const float4*)(vp0 + 4);

    uint32_t* pw = Ps[w];

    for (int t = 0; t < 32; t++) {
        const int cur = t & 1;
        __syncthreads();   // prev tile fully consumed (Vp, Ps, Kp[cur^1])
        {
            const float vv[8] = { rv0.x, rv0.y, rv0.z, rv0.w,
                                  rv1.x, rv1.y, rv1.z, rv1.w };
            #pragma unroll
            for (int j = 0; j < 8; j++) {
                const uint16_t hv = (uint16_t)(bfpack(vv[j], vv[j]) & 0xFFFFu);
                const uint32_t addr = vp_base + (uint32_t)((dseg + j) * 20 * 4) + vp_u16_off;
                asm volatile("st.shared.u16 [%0], %1;" :: "r"(addr), "h"(hv) : "memory");
            }
        }
        if (t + 1 < 32) {
            const uint32_t* kgn = kg + (size_t)(t + 1) * 32 * 32;
            cp16(sKp[cur ^ 1] + kdst,      kgn);
            cp16(sKp[cur ^ 1] + kdst + 16, kgn + 4);
            CP_COMMIT();
            CP_WAIT1();      // K(t) complete
        } else {
            CP_WAIT0();
        }
        __syncthreads();     // V stores + K(t) visible
        if (t + 1 < 32) {
            const size_t off = (size_t)(t + 1) * 32 * (3*DIM);
            rv0 = *(const float4*)(vp0 + off);
            rv1 = *(const float4*)(vp0 + off + 4);
        }

        const uint32_t* Kb = Kp[cur];

        float s[2][4][4];
        #pragma unroll
        for (int mt = 0; mt < 2; mt++)
            #pragma unroll
            for (int nt = 0; nt < 4; nt++)
                #pragma unroll
                for (int j = 0; j < 4; j++) s[mt][nt][j] = 0.f;

        #pragma unroll
        for (int nt = 0; nt < 4; nt++) {
            #pragma unroll
            for (int ks2 = 0; ks2 < 2; ks2++) {
                const int nb = (nt*8 + g)*40 + ks2*8 + 2*cth;
                const uint2 bh2 = *(const uint2*)(Kb + nb);
                const uint2 bl2 = *(const uint2*)(Kb + nb + 16);
                #pragma unroll
                for (int mt = 0; mt < 2; mt++) {
                    float* d = s[mt][nt];
                    const uint4 qh_ = qf[mt][ks2][0];
                    const uint4 ql_ = qf[mt][ks2][1];
                    mma16(d, qh_.x, qh_.y, qh_.z, qh_.w, bh2.x, bh2.y);
                    mma16(d, ql_.x, ql_.y, ql_.z, ql_.w, bh2.x, bh2.y);
                    mma16(d, qh_.x, qh_.y, qh_.z, qh_.w, bl2.x, bl2.y);
                }
            }
        }

        #pragma unroll
        for (int mt = 0; mt < 2; mt++) {
            #pragma unroll
            for (int r = 0; r < 2; r++) {
                float ts = 0.f;
                #pragma unroll
                for (int nt = 0; nt < 4; nt++) {
                    const float p0 = __expf(s[mt][nt][2*r]);
                    const float p1 = __expf(s[mt][nt][2*r+1]);
                    s[mt][nt][2*r]   = p0;
                    s[mt][nt][2*r+1] = p1;
                    ts += p0 + p1;
                }
                ts += __shfl_xor_sync(0xffffffffu, ts, 1);
                ts += __shfl_xor_sync(0xffffffffu, ts, 2);
                l_[mt][r] += ts;
            }
        }
        #pragma unroll
        for (int mt = 0; mt < 2; mt++)
            #pragma unroll
            for (int r = 0; r < 2; r++) {
                const int row = mt*16 + r*8 + g;
                #pragma unroll
                for (int nt = 0; nt < 4; nt++)
                    pw[row*20 + (nt>>1)*8 + 2*cth + (nt&1)] =
                        bfpack(s[mt][nt][2*r], s[mt][nt][2*r+1]);
            }
        __syncwarp();

        #pragma unroll
        for (int kc = 0; kc < 2; kc++) {
            uint2 a[2][2];
            #pragma unroll
            for (int mt = 0; mt < 2; mt++) {
                a[mt][0] = *(const uint2*)(pw + (mt*16 + g)*20 + kc*8 + 2*cth);
                a[mt][1] = *(const uint2*)(pw + (mt*16 + 8 + g)*20 + kc*8 + 2*cth);
            }
            #pragma unroll
            for (int nt = 0; nt < 4; nt++) {
                const uint2 bv = *(const uint2*)(Vp + (nt*8 + g)*20 + kc*8 + 2*cth);
                #pragma unroll
                for (int mt = 0; mt < 2; mt++)
                    mma16(o[mt][nt], a[mt][0].x, a[mt][1].x, a[mt][0].y, a[mt][1].y,
                          bv.x, bv.y);
            }
        }
        __syncwarp();
    }

    #pragma unroll
    for (int mt = 0; mt < 2; mt++) {
        #pragma unroll
        for (int r = 0; r < 2; r++) {
            const float inv = 1.f / l_[mt][r];
            const int row = qbase + mt*16 + r*8 + g;
            float* orow = g_attn + (size_t)(b * SEQ + row) * DIM + h * HDIM;
            #pragma unroll
            for (int nt = 0; nt < 4; nt++) {
                float2 v = make_float2(o[mt][nt][2*r] * inv,
                                       o[mt][nt][2*r+1] * inv);
                *(float2*)(orow + nt*8 + 2*cth) = v;
            }
        }
    }
}

// ---------------- node mask from post-projection h ---------------------------
__global__ void __launch_bounds__(256) mask_k()
{
    const int warp = threadIdx.x >> 5;
    const int lane = threadIdx.x & 31;
    const int row  = blockIdx.x * 8 + warp;
    const float* r = g_h + (size_t)row * DIM;
    float s = 0.f;
    #pragma unroll
    for (int i = 0; i < 4; i++) s += r[lane + 32*i];
    #pragma unroll
    for (int off = 16; off; off >>= 1) s += __shfl_xor_sync(~0u, s, off);
    if (lane == 0) g_mask[row] = (s != 0.f) ? 1.f : 0.f;
}

// ---------------- masked mean pooling (2 stage) -----------------------------
__global__ void __launch_bounds__(DIM) pool1_k()
{
    const int b  = blockIdx.y;
    const int c  = blockIdx.x;
    const int d  = threadIdx.x;
    float acc = 0.f, ms = 0.f;
    const int r0 = b * SEQ + c * 128;
    for (int r = 0; r < 128; r++) {
        const float mk = g_mask[r0 + r];
        acc = fmaf(g_h[(size_t)(r0 + r) * DIM + d], mk, acc);
        ms += mk;
    }
    g_pool[(b * 8 + c) * DIM + d] = acc;
    if (d == 0) g_pm[b * 8 + c] = ms;
}

__global__ void __launch_bounds__(DIM) pool2_k(float* __restrict__ out)
{
    const int b = blockIdx.x;
    const int d = threadIdx.x;
    float acc = 0.f, ms = 0.f;
    #pragma unroll
    for (int c = 0; c < 8; c++) {
        acc += g_pool[(b * 8 + c) * DIM + d];
        ms  += g_pm[b * 8 + c];
    }
    out[b * DIM + d] = acc / ms;
}

// ---------------- driver -----------------------------------------------------
extern "C" void kernel_launch(void* const* d_in, const int* in_sizes, int n_in,
                              void* d_out, int out_size)
{
    const float* x     = (const float*)d_in[0];   // [N, 64]
    const float* W_in  = (const float*)d_in[2];   // [128, 64]
    const float* b_in  = (const float*)d_in[3];   // [128]
    const float* Wqkv  = (const float*)d_in[4];   // [L, 384, 128]
    const float* bqkv  = (const float*)d_in[5];   // [L, 384]
    const float* Wo    = (const float*)d_in[6];   // [L, 128, 128]
    const float* bo    = (const float*)d_in[7];   // [L, 128]
    const float* W1    = (const float*)d_in[8];   // [L, 2048, 128]
    const float* b1    = (const float*)d_in[9];   // [L, 2048]
    const float* W2    = (const float*)d_in[10];  // [L, 128, 2048]
    const float* b2    = (const float*)d_in[11];  // [L, 128]
    const float* ln1g  = (const float*)d_in[12];
    const float* ln1b  = (const float*)d_in[13];
    const float* ln2g  = (const float*)d_in[14];
    const float* ln2b  = (const float*)d_in[15];
    float* out = (float*)d_out;

    static bool attr_done = false;
    if (!attr_done) {
        cudaFuncSetAttribute(gemm_k<false, false, false>,
            cudaFuncAttributeMaxDynamicSharedMemorySize, SMEM_G);
        cudaFuncSetAttribute(gemm_k<false, false, true>,
            cudaFuncAttributeMaxDynamicSharedMemorySize, SMEM_G);
        cudaFuncSetAttribute(gemm_k<true, false, false>,
            cudaFuncAttributeMaxDynamicSharedMemorySize, SMEM_G);
        cudaFuncSetAttribute(gemm_k<false, true, false>,
            cudaFuncAttributeMaxDynamicSharedMemorySize, SMEM_G);
        attr_done = true;
    }

    wsplit_k<<<dim3(512, 1 + 4*NLAY), 256>>>(W_in, Wqkv, Wo, W1, W2);

    const int MROW = NTOT / 128;   // 256 row-tiles

    gemm_k<false, false, false><<<dim3(1, MROW), 256, SMEM_G>>>(
        5, x, OFF_WIN, b_in, 0, DIM, INDIM, nullptr, nullptr);
    mask_k<<<NTOT/8, 256>>>();

    for (int l = 0; l < NLAY; l++) {
        // QKV: also emits packed K tiles to g_kp (blockIdx.x==1)
        gemm_k<false, false, true><<<dim3(3, MROW), 256, SMEM_G>>>(
            0, nullptr, OFF_QKV(l), bqkv + l*3*DIM, 1, 3*DIM, DIM, nullptr, nullptr);
        attn_k<<<NB*NHEAD*(SEQ/128), 128>>>();
        gemm_k<false, true, false><<<dim3(1, MROW), 256, SMEM_G>>>(
            2, nullptr, OFF_WO(l), bo + l*DIM, 0, DIM, DIM,
            ln1g + l*DIM, ln1b + l*DIM);
        gemm_k<true, false, false><<<dim3(DFF/128, MROW), 256, SMEM_G>>>(
            0, nullptr, OFF_W1(l), b1 + l*DFF, 4, DFF, DIM, nullptr, nullptr);
        gemm_k<false, true, false><<<dim3(1, MROW), 256, SMEM_G>>>(
            4, nullptr, OFF_W2(l), b2 + l*DIM, 0, DIM, DFF,
            ln2g + l*DIM, ln2b + l*DIM);
    }

    pool1_k<<<dim3(8, NB), DIM>>>();
    pool2_k<<<NB, DIM>>>(out);
}